// round 9
// baseline (speedup 1.0000x reference)
#include <cuda_runtime.h>
#include <cuda_bf16.h>
#include <cstdint>
#include <math.h>

#define EMBED 1024
#define HEADS 16
#define HDIM  64
#define BATCH 2
#define SEQ   2048
#define MTOT  (BATCH*SEQ)   // 4096
#define KCAT  3072          // 3*EMBED (split-bf16 concat)
#define KATT  192           // 3*HDIM  (split concat for attention)

// ---------------- scratch (device globals; no allocation allowed) ----------
__device__ float g_WeffQ[EMBED*EMBED];
__device__ float g_WeffK[EMBED*EMBED];
__device__ float g_beffQ[EMBED];
__device__ float g_beffK[EMBED];
__device__ __align__(256) __nv_bfloat16 g_Xcat[MTOT*KCAT];      // [m][3072] = [Xh|Xh|Xl]
__device__ __align__(256) __nv_bfloat16 g_WcatQ[EMBED*KCAT];    // [n][3072] = [Wh|Wl|Wh]
__device__ __align__(256) __nv_bfloat16 g_WcatK[EMBED*KCAT];
__device__ __align__(256) __nv_bfloat16 g_WcatV[EMBED*KCAT];
__device__ __align__(256) __nv_bfloat16 g_Qc[32*SEQ*KATT];      // [hb][n][192] = [Qh|Qh|Ql]*0.125
__device__ __align__(256) __nv_bfloat16 g_Kc[32*SEQ*KATT];      // [hb][n][192] = [Kh|Kl|Kh]
__device__ __align__(256) __nv_bfloat16 g_Vc[32*32*KATT*HDIM];  // [hb][tile][keycat 192][d 64]

// ======================= PTX helpers (sm_80-level) =========================
__device__ __forceinline__ uint32_t smem_u32(const void* p) {
    uint32_t a;
    asm("{ .reg .u64 t; cvta.to.shared.u64 t, %1; cvt.u32.u64 %0, t; }" : "=r"(a) : "l"(p));
    return a;
}
__device__ __forceinline__ void cp16(uint32_t s, const void* g) {
    asm volatile("cp.async.cg.shared.global [%0], [%1], 16;" :: "r"(s), "l"(g));
}
#define CP_COMMIT() asm volatile("cp.async.commit_group;" ::: "memory")
#define CP_WAIT1()  asm volatile("cp.async.wait_group 1;" ::: "memory")
#define CP_WAIT0()  asm volatile("cp.async.wait_group 0;" ::: "memory")

__device__ __forceinline__ void mma16816(float* c, const uint32_t* a, uint32_t b0, uint32_t b1) {
    asm volatile("mma.sync.aligned.m16n8k16.row.col.f32.bf16.bf16.f32 "
        "{%0,%1,%2,%3}, {%4,%5,%6,%7}, {%8,%9}, {%0,%1,%2,%3};"
        : "+f"(c[0]), "+f"(c[1]), "+f"(c[2]), "+f"(c[3])
        : "r"(a[0]), "r"(a[1]), "r"(a[2]), "r"(a[3]), "r"(b0), "r"(b1));
}
__device__ __forceinline__ void ldm4(uint32_t* r, uint32_t addr) {
    asm volatile("ldmatrix.sync.aligned.m8n8.x4.shared.b16 {%0,%1,%2,%3}, [%4];"
        : "=r"(r[0]), "=r"(r[1]), "=r"(r[2]), "=r"(r[3]) : "r"(addr));
}
__device__ __forceinline__ void ldm4t(uint32_t* r, uint32_t addr) {
    asm volatile("ldmatrix.sync.aligned.m8n8.x4.trans.shared.b16 {%0,%1,%2,%3}, [%4];"
        : "=r"(r[0]), "=r"(r[1]), "=r"(r[2]), "=r"(r[3]) : "r"(addr));
}
__device__ __forceinline__ uint32_t packbf2(__nv_bfloat16 lo, __nv_bfloat16 hi) {
    __nv_bfloat162 t; t.x = lo; t.y = hi;
    return *(uint32_t*)&t;
}

// ---------------------------------------------------------------------------
// Fold per-head Wp into Wq / Wk (and biases).
// ---------------------------------------------------------------------------
__global__ void build_eff(const float* __restrict__ Wq, const float* __restrict__ bq,
                          const float* __restrict__ Wk, const float* __restrict__ bk,
                          const float* __restrict__ Wp)
{
    __shared__ float WpS[64*64];
    int i = threadIdx.x;
    for (int t = i; t < 64*64; t += 64) WpS[t] = Wp[t];
    __syncthreads();

    int h = blockIdx.y;
    int e = blockIdx.x;
    const float* W    = blockIdx.z ? Wk      : Wq;
    const float* b    = blockIdx.z ? bk      : bq;
    float*       Weff = blockIdx.z ? g_WeffK : g_WeffQ;
    float*       beff = blockIdx.z ? g_beffK : g_beffQ;

    float acc = 0.f;
    if (e < EMBED) {
        const float* src = W + e*EMBED + h*HDIM;
        #pragma unroll 8
        for (int d = 0; d < 64; d++) acc = fmaf(src[d], WpS[d*64 + i], acc);
        Weff[e*EMBED + h*HDIM + i] = acc;
    } else {
        const float* src = b + h*HDIM;
        #pragma unroll 8
        for (int d = 0; d < 64; d++) acc = fmaf(src[d], WpS[d*64 + i], acc);
        beff[h*HDIM + i] = acc;
    }
}

// ---------------------------------------------------------------------------
// Fused converts: blocks [0,8192) do X; [8192, 8192+3072) do W (z = Q/K/V).
// ---------------------------------------------------------------------------
__global__ void convert_XW(const float* __restrict__ x, const float* __restrict__ Wv)
{
    __shared__ float tile[32][33];
    int bx = blockIdx.x;
    int tid = threadIdx.x;

    if (bx < 8192) {
        int t = bx*256 + tid;
        float2 v = ((const float2*)x)[t];
        int m = t >> 9;
        int e = (t & 511) << 1;
        __nv_bfloat16 hx = __float2bfloat16(v.x), hy = __float2bfloat16(v.y);
        __nv_bfloat16 lx = __float2bfloat16(v.x - __bfloat162float(hx));
        __nv_bfloat16 ly = __float2bfloat16(v.y - __bfloat162float(hy));
        __nv_bfloat162 hi; hi.x = hx; hi.y = hy;
        __nv_bfloat162 lo; lo.x = lx; lo.y = ly;
        size_t base = (size_t)m*KCAT + e;
        *(__nv_bfloat162*)&g_Xcat[base        ] = hi;
        *(__nv_bfloat162*)&g_Xcat[base + 1024 ] = hi;
        *(__nv_bfloat162*)&g_Xcat[base + 2048 ] = lo;
        return;
    }

    int wb = bx - 8192;                 // 0..3071
    int z  = wb >> 10;                  // 0=Q, 1=K, 2=V
    int rem = wb & 1023;
    int k0 = (rem >> 5) * 32;           // 32 k-blocks
    int n0 = (rem & 31) * 32;           // 32 n-blocks
    int tx = tid & 31, ty = tid >> 5;   // (32, 8)

    const float* src = (z == 0) ? g_WeffQ : (z == 1) ? g_WeffK : Wv;
    __nv_bfloat16* dst = (z == 0) ? g_WcatQ : (z == 1) ? g_WcatK : g_WcatV;
    #pragma unroll
    for (int j = 0; j < 32; j += 8)
        tile[ty+j][tx] = src[(size_t)(k0+ty+j)*EMBED + n0 + tx];
    __syncthreads();
    #pragma unroll
    for (int j = 0; j < 32; j += 8) {
        int n = ty + j;
        float v = tile[tx][n];
        __nv_bfloat16 hi = __float2bfloat16(v);
        __nv_bfloat16 lo = __float2bfloat16(v - __bfloat162float(hi));
        size_t base = (size_t)(n0+n)*KCAT + k0 + tx;
        dst[base       ] = hi;
        dst[base + 1024] = lo;
        dst[base + 2048] = hi;
    }
}

// ---------------------------------------------------------------------------
// HMMA GEMM (proven core: 2-stage, 8 warps, 128x128, BK=64).
// which: 0=Q (split-bf16, scaled 1/8), 1=K (split-bf16), 2=V (split-bf16,
// written to Vc [keycat][d] layout directly — no fp32 round-trip).
// ---------------------------------------------------------------------------
#define GSTAGE 32768
#define SMEM_GEMM (2*GSTAGE)
#define NCHUNK (KCAT/64)   // 48

__device__ __forceinline__ void gemm_load(const __nv_bfloat16* Bw,
                                          uint32_t sb, int stage, int m0, int n0,
                                          int chunk, int tid)
{
    uint32_t as = sb + stage*GSTAGE;
    uint32_t bs = as + 16384;
    const char* Ac = (const char*)g_Xcat;
    const char* Bc = (const char*)Bw;
    #pragma unroll
    for (int r = 0; r < 4; r++) {
        int idx = tid + r*256;
        int row = idx >> 3, sec = idx & 7;
        cp16(as + row*128 + (((sec ^ (row & 7))) << 4),
             Ac + ((size_t)(m0+row)*KCAT + chunk*64 + sec*8)*2);
    }
    #pragma unroll
    for (int r = 0; r < 4; r++) {
        int idx = tid + r*256;
        int row = idx >> 3, sec = idx & 7;
        cp16(bs + row*128 + (((sec ^ (row & 7))) << 4),
             Bc + ((size_t)(n0+row)*KCAT + chunk*64 + sec*8)*2);
    }
}

__global__ __launch_bounds__(256) void gemm_mma(
    const __nv_bfloat16* __restrict__ Bw,
    const float* __restrict__ bias, int which)
{
    extern __shared__ char smem[];
    uint32_t sb = smem_u32(smem);
    int tid = threadIdx.x, wid = tid >> 5, l = tid & 31;
    int m0 = blockIdx.x * 128, n0 = blockIdx.y * 128;
    int wm = (wid & 3) * 32, wn = (wid >> 2) * 64;

    float c[2][8][4];
    #pragma unroll
    for (int mi = 0; mi < 2; mi++)
        #pragma unroll
        for (int j = 0; j < 8; j++)
            #pragma unroll
            for (int e = 0; e < 4; e++) c[mi][j][e] = 0.f;

    gemm_load(Bw, sb, 0, m0, n0, 0, tid);
    CP_COMMIT();

    for (int i = 0; i < NCHUNK; i++) {
        if (i + 1 < NCHUNK) {
            gemm_load(Bw, sb, (i+1) & 1, m0, n0, i+1, tid);
            CP_COMMIT();
            CP_WAIT1();
        } else {
            CP_WAIT0();
        }
        __syncthreads();

        uint32_t as = sb + (i & 1)*GSTAGE;
        uint32_t bs = as + 16384;
        #pragma unroll
        for (int kk = 0; kk < 4; kk++) {
            uint32_t a0[4], a1[4];
            {
                int row = wm + (l & 15);
                int sec = 2*kk + (l >> 4);
                ldm4(a0, as + row*128 + ((sec ^ (row & 7)) << 4));
                row += 16;
                ldm4(a1, as + row*128 + ((sec ^ (row & 7)) << 4));
            }
            #pragma unroll
            for (int jp = 0; jp < 4; jp++) {
                uint32_t b[4];
                int row = wn + jp*16 + (l & 7) + ((l >> 4) << 3);
                int sec = 2*kk + ((l >> 3) & 1);
                ldm4(b, bs + row*128 + ((sec ^ (row & 7)) << 4));
                mma16816(c[0][2*jp],   a0, b[0], b[1]);
                mma16816(c[0][2*jp+1], a0, b[2], b[3]);
                mma16816(c[1][2*jp],   a1, b[0], b[1]);
                mma16816(c[1][2*jp+1], a1, b[2], b[3]);
            }
        }
        __syncthreads();
    }

    // ---- epilogue (all outputs split-bf16) ----
    #pragma unroll
    for (int mi = 0; mi < 2; mi++) {
        int mbase = m0 + wm + mi*16 + (l >> 2);
        #pragma unroll
        for (int j = 0; j < 8; j++) {
            int ncol = n0 + wn + j*8 + (l & 3)*2;
            float2 bb = *(const float2*)&bias[ncol];
            int h = ncol >> 6, d = ncol & 63;
            #pragma unroll
            for (int half = 0; half < 2; half++) {
                int m = mbase + half*8;
                int b_ = m >> 11, ns = m & (SEQ-1);
                float scale = (which == 0) ? 0.125f : 1.0f;
                float vx = (c[mi][j][2*half+0] + bb.x) * scale;
                float vy = (c[mi][j][2*half+1] + bb.y) * scale;
                __nv_bfloat16 h0 = __float2bfloat16(vx);
                __nv_bfloat16 h1 = __float2bfloat16(vy);
                __nv_bfloat162 hi2; hi2.x = h0; hi2.y = h1;
                __nv_bfloat162 lo2;
                lo2.x = __float2bfloat16(vx - __bfloat162float(h0));
                lo2.y = __float2bfloat16(vy - __bfloat162float(h1));
                if (which == 2) {
                    // Vc[hb][tile][keycat][d]: hi@key, lo@key+64, hi@key+128
                    size_t vb = (((size_t)(b_*HEADS + h)*32 + (ns >> 6))*KATT
                                 + (ns & 63))*HDIM + d;
                    *(__nv_bfloat162*)&g_Vc[vb           ] = hi2;
                    *(__nv_bfloat162*)&g_Vc[vb + 64*HDIM ] = lo2;
                    *(__nv_bfloat162*)&g_Vc[vb + 128*HDIM] = hi2;
                } else {
                    __nv_bfloat16* dc = (which == 0) ? g_Qc : g_Kc;
                    size_t qb = ((size_t)(b_*HEADS + h)*SEQ + ns)*KATT + d;
                    if (which == 0) {  // [Qh|Qh|Ql]
                        *(__nv_bfloat162*)&dc[qb      ] = hi2;
                        *(__nv_bfloat162*)&dc[qb + 64 ] = hi2;
                        *(__nv_bfloat162*)&dc[qb + 128] = lo2;
                    } else {           // [Kh|Kl|Kh]
                        *(__nv_bfloat162*)&dc[qb      ] = hi2;
                        *(__nv_bfloat162*)&dc[qb + 64 ] = lo2;
                        *(__nv_bfloat162*)&dc[qb + 128] = hi2;
                    }
                }
            }
        }
    }
}

// ---------------------------------------------------------------------------
// Flash attention on HMMA. 64 q-rows, 4 warps, Q fragments in REGISTERS,
// K and V double-buffered. V tiles are [keycat 192][d 64] (row-major),
// loaded as B-fragments via ldmatrix.trans.
// smem: K 2x25600 + V 2x27648 = 106496 B -> 2 CTAs/SM. grid (32, 32), 128 thr.
// ---------------------------------------------------------------------------
#define ROWB 400            // K/Q smem pitch (64 rows x 384B data)
#define VROWB 144           // V smem pitch (192 rows x 128B data)
#define KB0 0
#define KB1 25600
#define VB0 51200
#define VB1 78848
#define SMEM_ATT 106496
#define VTILE_B (KATT*HDIM*2)   // 24576 B per V tile in gmem

__device__ __forceinline__ void att_load_k(uint32_t dst, const char* src, int tid)
{
    #pragma unroll
    for (int r = 0; r < 12; r++) {          // 64 rows x 24 sectors (16B)
        int idx = tid + r*128;
        int row = idx / 24, sec = idx % 24;
        cp16(dst + row*ROWB + sec*16, src + row*384 + sec*16);
    }
}
__device__ __forceinline__ void att_load_v(uint32_t dst, const char* src, int tid)
{
    #pragma unroll
    for (int r = 0; r < 12; r++) {          // 192 rows x 8 sectors (16B)
        int idx = tid + r*128;
        int row = idx >> 3, sec = idx & 7;
        cp16(dst + row*VROWB + sec*16, src + row*128 + sec*16);
    }
}

__global__ __launch_bounds__(128) void attn_mma(float* __restrict__ out)
{
    extern __shared__ char smem[];
    uint32_t sb = smem_u32(smem);
    int tid = threadIdx.x, wid = tid >> 5, l = tid & 31;
    int hb = blockIdx.y, q0 = blockIdx.x * 64;

    const char* Qg = (const char*)(g_Qc + ((size_t)hb*SEQ + q0)*KATT);
    const char* Kg = (const char*)(g_Kc + (size_t)hb*SEQ*KATT);
    const char* Vg = (const char*)(g_Vc + (size_t)hb*32*KATT*HDIM);

    // startup: Q->VB1 (K-pitch) + K0->KB0 (group 1);  V0->VB0 (group 2)
    att_load_k(sb + VB1, Qg, tid);
    att_load_k(sb + KB0, Kg, tid);
    CP_COMMIT();
    att_load_v(sb + VB0, Vg, tid);
    CP_COMMIT();

    CP_WAIT1();                          // Q + K0 ready
    __syncthreads();

    // Q fragments -> registers (loop-invariant)
    uint32_t qf[12][4];
    #pragma unroll
    for (int kk = 0; kk < 12; kk++) {
        int row = wid*16 + (l & 15);
        int sec = 2*kk + (l >> 4);
        ldm4(qf[kk], sb + VB1 + row*ROWB + sec*16);
    }

    float o[8][4];
    #pragma unroll
    for (int j = 0; j < 8; j++)
        #pragma unroll
        for (int e = 0; e < 4; e++) o[j][e] = 0.f;
    float m0r = -1e30f, m1r = -1e30f, l0r = 0.f, l1r = 0.f;

    for (int i = 0; i < 32; i++) {
        CP_WAIT1();                      // K_i complete (V_i may pend)
        __syncthreads();
        if (i + 1 < 32) {
            att_load_k(sb + (((i+1) & 1) ? KB1 : KB0),
                       Kg + (size_t)(i+1)*64*384, tid);
            CP_COMMIT();
        }
        uint32_t kbase = sb + ((i & 1) ? KB1 : KB0);

        // ---- S = Qcat @ Kcat^T ----
        float s[8][4];
        #pragma unroll
        for (int j = 0; j < 8; j++)
            #pragma unroll
            for (int e = 0; e < 4; e++) s[j][e] = 0.f;

        #pragma unroll
        for (int kk = 0; kk < 12; kk++) {
            #pragma unroll
            for (int jp = 0; jp < 4; jp++) {
                uint32_t b[4];
                int row = jp*16 + (l & 7) + ((l >> 4) << 3);
                int sec = 2*kk + ((l >> 3) & 1);
                ldm4(b, kbase + row*ROWB + sec*16);
                mma16816(s[2*jp],   qf[kk], b[0], b[1]);
                mma16816(s[2*jp+1], qf[kk], b[2], b[3]);
            }
        }

        // ---- online softmax ----
        float rmax0 = -1e30f, rmax1 = -1e30f;
        #pragma unroll
        for (int j = 0; j < 8; j++) {
            rmax0 = fmaxf(rmax0, fmaxf(s[j][0], s[j][1]));
            rmax1 = fmaxf(rmax1, fmaxf(s[j][2], s[j][3]));
        }
        rmax0 = fmaxf(rmax0, __shfl_xor_sync(0xffffffffu, rmax0, 1));
        rmax0 = fmaxf(rmax0, __shfl_xor_sync(0xffffffffu, rmax0, 2));
        rmax1 = fmaxf(rmax1, __shfl_xor_sync(0xffffffffu, rmax1, 1));
        rmax1 = fmaxf(rmax1, __shfl_xor_sync(0xffffffffu, rmax1, 2));
        float nm0 = fmaxf(m0r, rmax0), nm1 = fmaxf(m1r, rmax1);
        float rs0 = 0.f, rs1 = 0.f;
        #pragma unroll
        for (int j = 0; j < 8; j++) {
            s[j][0] = __expf(s[j][0] - nm0);
            s[j][1] = __expf(s[j][1] - nm0);
            s[j][2] = __expf(s[j][2] - nm1);
            s[j][3] = __expf(s[j][3] - nm1);
            rs0 += s[j][0] + s[j][1];
            rs1 += s[j][2] + s[j][3];
        }
        rs0 += __shfl_xor_sync(0xffffffffu, rs0, 1);
        rs0 += __shfl_xor_sync(0xffffffffu, rs0, 2);
        rs1 += __shfl_xor_sync(0xffffffffu, rs1, 1);
        rs1 += __shfl_xor_sync(0xffffffffu, rs1, 2);
        float al0 = __expf(m0r - nm0), al1 = __expf(m1r - nm1);
        l0r = l0r*al0 + rs0;  l1r = l1r*al1 + rs1;
        m0r = nm0;  m1r = nm1;
        #pragma unroll
        for (int j = 0; j < 8; j++) {
            o[j][0] *= al0; o[j][1] *= al0;
            o[j][2] *= al1; o[j][3] *= al1;
        }

        // ---- pack P (hi + residual lo) into A fragments ----
        uint32_t ph[4][4], pl[4][4];
        #pragma unroll
        for (int kk = 0; kk < 4; kk++) {
            #pragma unroll
            for (int half = 0; half < 2; half++) {
                #pragma unroll
                for (int sub = 0; sub < 2; sub++) {
                    float p0 = s[2*kk+sub][2*half+0];
                    float p1 = s[2*kk+sub][2*half+1];
                    __nv_bfloat16 h0 = __float2bfloat16(p0);
                    __nv_bfloat16 h1 = __float2bfloat16(p1);
                    ph[kk][2*sub+half] = packbf2(h0, h1);
                    pl[kk][2*sub+half] = packbf2(
                        __float2bfloat16(p0 - __bfloat162float(h0)),
                        __float2bfloat16(p1 - __bfloat162float(h1)));
                }
            }
        }

        // ---- O += Pcat @ Vcat  (V in [keycat][d], B-frags via ldsm.trans) ----
        if (i + 1 < 32) { CP_WAIT1(); } else { CP_WAIT0(); }   // V_i complete
        __syncthreads();
        if (i + 1 < 32) {
            att_load_v(sb + (((i+1) & 1) ? VB1 : VB0),
                       Vg + (size_t)(i+1)*VTILE_B, tid);
            CP_COMMIT();
        }
        uint32_t vbase = sb + ((i & 1) ? VB1 : VB0);
        #pragma unroll
        for (int kb = 0; kb < 12; kb++) {
            const uint32_t* a = (kb < 4) ? ph[kb] : (kb < 8) ? ph[kb-4] : pl[kb-8];
            #pragma unroll
            for (int jp = 0; jp < 4; jp++) {
                uint32_t b[4];
                int row = kb*16 + (l & 7) + (((l >> 3) & 1) << 3);  // k-row
                int colb = jp*32 + ((l >> 4) << 4);                  // d-col bytes
                ldm4t(b, vbase + row*VROWB + colb);
                mma16816(o[2*jp],   a, b[0], b[1]);
                mma16816(o[2*jp+1], a, b[2], b[3]);
            }
        }
    }

    // ---- epilogue ----
    int b_ = hb >> 4, h = hb & 15;
    float inv0 = 1.f / l0r, inv1 = 1.f / l1r;
    int r0 = q0 + wid*16 + (l >> 2);
    #pragma unroll
    for (int j = 0; j < 8; j++) {
        int d = j*8 + (l & 3)*2;
        float2 v0; v0.x = o[j][0]*inv0; v0.y = o[j][1]*inv0;
        float2 v1; v1.x = o[j][2]*inv1; v1.y = o[j][3]*inv1;
        *(float2*)&out[((size_t)(b_*SEQ + r0  ))*EMBED + h*HDIM + d] = v0;
        *(float2*)&out[((size_t)(b_*SEQ + r0+8))*EMBED + h*HDIM + d] = v1;
    }
}

// ---------------------------------------------------------------------------
extern "C" void kernel_launch(void* const* d_in, const int* in_sizes, int n_in,
                              void* d_out, int out_size)
{
    const float* x  = (const float*)d_in[0];
    const float* Wq = (const float*)d_in[1];
    const float* bq = (const float*)d_in[2];
    const float* Wk = (const float*)d_in[3];
    const float* bk = (const float*)d_in[4];
    const float* Wv = (const float*)d_in[5];
    const float* bv = (const float*)d_in[6];
    const float* Wp = (const float*)d_in[7];
    float* out = (float*)d_out;

    cudaFuncSetAttribute(gemm_mma, cudaFuncAttributeMaxDynamicSharedMemorySize, SMEM_GEMM);
    cudaFuncSetAttribute(attn_mma, cudaFuncAttributeMaxDynamicSharedMemorySize, SMEM_ATT);

    float *pbeffQ, *pbeffK;
    __nv_bfloat16 *pWcatQ, *pWcatK, *pWcatV;
    cudaGetSymbolAddress((void**)&pbeffQ, g_beffQ);
    cudaGetSymbolAddress((void**)&pbeffK, g_beffK);
    cudaGetSymbolAddress((void**)&pWcatQ, g_WcatQ);
    cudaGetSymbolAddress((void**)&pWcatK, g_WcatK);
    cudaGetSymbolAddress((void**)&pWcatV, g_WcatV);

    build_eff<<<dim3(EMBED+1, HEADS, 2), 64>>>(Wq, bq, Wk, bk, Wp);          // #1
    convert_XW<<<8192 + 3072, 256>>>(x, Wv);                                 // #2

    gemm_mma<<<dim3(MTOT/128, EMBED/128), 256, SMEM_GEMM>>>(pWcatQ, pbeffQ, 0); // #3
    gemm_mma<<<dim3(MTOT/128, EMBED/128), 256, SMEM_GEMM>>>(pWcatK, pbeffK, 1); // #4
    gemm_mma<<<dim3(MTOT/128, EMBED/128), 256, SMEM_GEMM>>>(pWcatV, bv,     2); // #5

    attn_mma<<<dim3(SEQ/64, BATCH*HEADS), 128, SMEM_ATT>>>(out);             // #6 (profiled)
}

// round 10
// speedup vs baseline: 1.1943x; 1.1943x over previous
#include <cuda_runtime.h>
#include <cuda_bf16.h>
#include <cstdint>
#include <math.h>

#define EMBED 1024
#define HEADS 16
#define HDIM  64
#define BATCH 2
#define SEQ   2048
#define MTOT  (BATCH*SEQ)   // 4096
#define KCAT  3072          // 3*EMBED (split-bf16 concat)
#define KATT  192           // 3*HDIM  (split concat for attention)

// ---------------- scratch (device globals; no allocation allowed) ----------
__device__ float g_beffQ[EMBED];
__device__ float g_beffK[EMBED];
__device__ __align__(256) __nv_bfloat16 g_Xcat[MTOT*KCAT];      // [m][3072] = [Xh|Xh|Xl]
__device__ __align__(256) __nv_bfloat16 g_WcatQ[EMBED*KCAT];    // [n][3072] = [Wh|Wl|Wh]
__device__ __align__(256) __nv_bfloat16 g_WcatK[EMBED*KCAT];
__device__ __align__(256) __nv_bfloat16 g_WcatV[EMBED*KCAT];
__device__ __align__(256) __nv_bfloat16 g_Qc[32*SEQ*KATT];      // [hb][n][192] = [Qh|Qh|Ql]*0.125
__device__ __align__(256) __nv_bfloat16 g_Kc[32*SEQ*KATT];      // [hb][n][192] = [Kh|Kl|Kh]
__device__ __align__(256) __nv_bfloat16 g_Vc[32*32*KATT*HDIM];  // [hb][tile][keycat 192][d 64]

// ======================= PTX helpers (sm_80-level) =========================
__device__ __forceinline__ uint32_t smem_u32(const void* p) {
    uint32_t a;
    asm("{ .reg .u64 t; cvta.to.shared.u64 t, %1; cvt.u32.u64 %0, t; }" : "=r"(a) : "l"(p));
    return a;
}
__device__ __forceinline__ void cp16(uint32_t s, const void* g) {
    asm volatile("cp.async.cg.shared.global [%0], [%1], 16;" :: "r"(s), "l"(g));
}
#define CP_COMMIT() asm volatile("cp.async.commit_group;" ::: "memory")
#define CP_WAIT1()  asm volatile("cp.async.wait_group 1;" ::: "memory")
#define CP_WAIT0()  asm volatile("cp.async.wait_group 0;" ::: "memory")

__device__ __forceinline__ void mma16816(float* c, const uint32_t* a, uint32_t b0, uint32_t b1) {
    asm volatile("mma.sync.aligned.m16n8k16.row.col.f32.bf16.bf16.f32 "
        "{%0,%1,%2,%3}, {%4,%5,%6,%7}, {%8,%9}, {%0,%1,%2,%3};"
        : "+f"(c[0]), "+f"(c[1]), "+f"(c[2]), "+f"(c[3])
        : "r"(a[0]), "r"(a[1]), "r"(a[2]), "r"(a[3]), "r"(b0), "r"(b1));
}
__device__ __forceinline__ void ldm4(uint32_t* r, uint32_t addr) {
    asm volatile("ldmatrix.sync.aligned.m8n8.x4.shared.b16 {%0,%1,%2,%3}, [%4];"
        : "=r"(r[0]), "=r"(r[1]), "=r"(r[2]), "=r"(r[3]) : "r"(addr));
}
__device__ __forceinline__ void ldm4t(uint32_t* r, uint32_t addr) {
    asm volatile("ldmatrix.sync.aligned.m8n8.x4.trans.shared.b16 {%0,%1,%2,%3}, [%4];"
        : "=r"(r[0]), "=r"(r[1]), "=r"(r[2]), "=r"(r[3]) : "r"(addr));
}
__device__ __forceinline__ uint32_t packbf2(__nv_bfloat16 lo, __nv_bfloat16 hi) {
    __nv_bfloat162 t; t.x = lo; t.y = hi;
    return *(uint32_t*)&t;
}

// ---------------------------------------------------------------------------
// ONE prep kernel, block-range dispatch:
//   [0, 8192)        : X -> split-bf16 K-concat
//   [8192, 10240)    : Wq/Wk: fold Wp AND split-convert (32x32 Weff tile)
//   [10240, 11264)   : Wv: transpose + split-convert
//   [11264, 11266)   : bias fold for Q / K
// ---------------------------------------------------------------------------
__global__ __launch_bounds__(256) void prep_all(
    const float* __restrict__ x,
    const float* __restrict__ Wq, const float* __restrict__ bq,
    const float* __restrict__ Wk, const float* __restrict__ bk,
    const float* __restrict__ Wv, const float* __restrict__ Wp)
{
    __shared__ float tile[32][33];
    __shared__ float WrowS[32][65];
    __shared__ float WpS[64][32];
    int bx = blockIdx.x;
    int tid = threadIdx.x;

    if (bx < 8192) {                                   // ---- X convert ----
        int t = bx*256 + tid;
        float2 v = ((const float2*)x)[t];
        int m = t >> 9;
        int e = (t & 511) << 1;
        __nv_bfloat16 hx = __float2bfloat16(v.x), hy = __float2bfloat16(v.y);
        __nv_bfloat16 lx = __float2bfloat16(v.x - __bfloat162float(hx));
        __nv_bfloat16 ly = __float2bfloat16(v.y - __bfloat162float(hy));
        __nv_bfloat162 hi; hi.x = hx; hi.y = hy;
        __nv_bfloat162 lo; lo.x = lx; lo.y = ly;
        size_t base = (size_t)m*KCAT + e;
        *(__nv_bfloat162*)&g_Xcat[base        ] = hi;
        *(__nv_bfloat162*)&g_Xcat[base + 1024 ] = hi;
        *(__nv_bfloat162*)&g_Xcat[base + 2048 ] = lo;
        return;
    }

    int tx = tid & 31, ty = tid >> 5;                  // (32, 8)

    if (bx < 10240) {                                  // ---- Wq/Wk fold+convert ----
        int wb = bx - 8192;
        int z  = wb >> 10;                             // 0=Q, 1=K
        int rem = wb & 1023;
        int e0 = (rem >> 5) * 32;
        int n0 = (rem & 31) * 32;
        int h  = n0 >> 6, i0 = n0 & 63;
        const float* W = z ? Wk : Wq;
        __nv_bfloat16* dst = z ? g_WcatK : g_WcatQ;

        // stage W rows [e0,e0+32) x d 64  and Wp[0..63][i0..i0+32)
        #pragma unroll
        for (int r = 0; r < 8; r++) {
            int idx = tid + r*256;                     // 2048 elems
            int e = idx >> 6, d = idx & 63;
            WrowS[e][d] = W[(size_t)(e0+e)*EMBED + h*HDIM + d];
            int dd = idx >> 5, ni = idx & 31;
            WpS[dd][ni] = Wp[dd*HDIM + i0 + ni];
        }
        __syncthreads();
        // eff[e][n] = sum_d WrowS[e][d] * WpS[d][n]
        #pragma unroll
        for (int j = 0; j < 32; j += 8) {
            int n = ty + j;
            float acc = 0.f;
            #pragma unroll 8
            for (int d = 0; d < 64; d++)
                acc = fmaf(WrowS[tx][d], WpS[d][n], acc);
            tile[tx][n] = acc;
        }
        __syncthreads();
        #pragma unroll
        for (int j = 0; j < 32; j += 8) {
            int n = ty + j;
            float v = tile[tx][n];
            __nv_bfloat16 hi = __float2bfloat16(v);
            __nv_bfloat16 lo = __float2bfloat16(v - __bfloat162float(hi));
            size_t base = (size_t)(n0+n)*KCAT + e0 + tx;
            dst[base       ] = hi;
            dst[base + 1024] = lo;
            dst[base + 2048] = hi;
        }
        return;
    }

    if (bx < 11264) {                                  // ---- Wv transpose+convert ----
        int rem = bx - 10240;
        int k0 = (rem >> 5) * 32;
        int n0 = (rem & 31) * 32;
        #pragma unroll
        for (int j = 0; j < 32; j += 8)
            tile[ty+j][tx] = Wv[(size_t)(k0+ty+j)*EMBED + n0 + tx];
        __syncthreads();
        #pragma unroll
        for (int j = 0; j < 32; j += 8) {
            int n = ty + j;
            float v = tile[tx][n];
            __nv_bfloat16 hi = __float2bfloat16(v);
            __nv_bfloat16 lo = __float2bfloat16(v - __bfloat162float(hi));
            size_t base = (size_t)(n0+n)*KCAT + k0 + tx;
            g_WcatV[base       ] = hi;
            g_WcatV[base + 1024] = lo;
            g_WcatV[base + 2048] = hi;
        }
        return;
    }

    // ---- bias fold: beff[n] = sum_d b[h*64+d] * Wp[d][n&63] ----
    {
        int z = bx - 11264;                            // 0=Q, 1=K
        const float* b = z ? bk : bq;
        float* beff = z ? g_beffK : g_beffQ;
        #pragma unroll
        for (int r = 0; r < 4; r++) {
            int n = tid + r*256;
            int h = n >> 6, i = n & 63;
            float acc = 0.f;
            #pragma unroll 8
            for (int d = 0; d < 64; d++)
                acc = fmaf(b[h*HDIM + d], Wp[d*HDIM + i], acc);
            beff[n] = acc;
        }
    }
}

// ---------------------------------------------------------------------------
// Fused QKV HMMA GEMM, one launch. grid (32, 24): which = by>>3.
// Proven 2-stage core; split-bf16 epilogues (Q/K -> Qc/Kc, V -> Vc).
// ---------------------------------------------------------------------------
#define GSTAGE 32768
#define SMEM_GEMM (2*GSTAGE)
#define NCHUNK (KCAT/64)   // 48

__device__ __forceinline__ void gemm_load(const __nv_bfloat16* Bw,
                                          uint32_t sb, int stage, int m0, int n0,
                                          int chunk, int tid)
{
    uint32_t as = sb + stage*GSTAGE;
    uint32_t bs = as + 16384;
    const char* Ac = (const char*)g_Xcat;
    const char* Bc = (const char*)Bw;
    #pragma unroll
    for (int r = 0; r < 4; r++) {
        int idx = tid + r*256;
        int row = idx >> 3, sec = idx & 7;
        cp16(as + row*128 + (((sec ^ (row & 7))) << 4),
             Ac + ((size_t)(m0+row)*KCAT + chunk*64 + sec*8)*2);
    }
    #pragma unroll
    for (int r = 0; r < 4; r++) {
        int idx = tid + r*256;
        int row = idx >> 3, sec = idx & 7;
        cp16(bs + row*128 + (((sec ^ (row & 7))) << 4),
             Bc + ((size_t)(n0+row)*KCAT + chunk*64 + sec*8)*2);
    }
}

__global__ __launch_bounds__(256) void gemm_mma(const float* __restrict__ bv)
{
    extern __shared__ char smem[];
    uint32_t sb = smem_u32(smem);
    int tid = threadIdx.x, wid = tid >> 5, l = tid & 31;
    int which = blockIdx.y >> 3;                       // 0=Q, 1=K, 2=V
    int m0 = blockIdx.x * 128, n0 = (blockIdx.y & 7) * 128;
    int wm = (wid & 3) * 32, wn = (wid >> 2) * 64;

    const __nv_bfloat16* Bw = (which == 0) ? g_WcatQ : (which == 1) ? g_WcatK : g_WcatV;
    const float* bias = (which == 0) ? g_beffQ : (which == 1) ? g_beffK : bv;

    float c[2][8][4];
    #pragma unroll
    for (int mi = 0; mi < 2; mi++)
        #pragma unroll
        for (int j = 0; j < 8; j++)
            #pragma unroll
            for (int e = 0; e < 4; e++) c[mi][j][e] = 0.f;

    gemm_load(Bw, sb, 0, m0, n0, 0, tid);
    CP_COMMIT();

    for (int i = 0; i < NCHUNK; i++) {
        if (i + 1 < NCHUNK) {
            gemm_load(Bw, sb, (i+1) & 1, m0, n0, i+1, tid);
            CP_COMMIT();
            CP_WAIT1();
        } else {
            CP_WAIT0();
        }
        __syncthreads();

        uint32_t as = sb + (i & 1)*GSTAGE;
        uint32_t bs = as + 16384;
        #pragma unroll
        for (int kk = 0; kk < 4; kk++) {
            uint32_t a0[4], a1[4];
            {
                int row = wm + (l & 15);
                int sec = 2*kk + (l >> 4);
                ldm4(a0, as + row*128 + ((sec ^ (row & 7)) << 4));
                row += 16;
                ldm4(a1, as + row*128 + ((sec ^ (row & 7)) << 4));
            }
            #pragma unroll
            for (int jp = 0; jp < 4; jp++) {
                uint32_t b[4];
                int row = wn + jp*16 + (l & 7) + ((l >> 4) << 3);
                int sec = 2*kk + ((l >> 3) & 1);
                ldm4(b, bs + row*128 + ((sec ^ (row & 7)) << 4));
                mma16816(c[0][2*jp],   a0, b[0], b[1]);
                mma16816(c[0][2*jp+1], a0, b[2], b[3]);
                mma16816(c[1][2*jp],   a1, b[0], b[1]);
                mma16816(c[1][2*jp+1], a1, b[2], b[3]);
            }
        }
        __syncthreads();
    }

    // ---- epilogue (all outputs split-bf16) ----
    #pragma unroll
    for (int mi = 0; mi < 2; mi++) {
        int mbase = m0 + wm + mi*16 + (l >> 2);
        #pragma unroll
        for (int j = 0; j < 8; j++) {
            int ncol = n0 + wn + j*8 + (l & 3)*2;
            float2 bb = *(const float2*)&bias[ncol];
            int h = ncol >> 6, d = ncol & 63;
            #pragma unroll
            for (int half = 0; half < 2; half++) {
                int m = mbase + half*8;
                int b_ = m >> 11, ns = m & (SEQ-1);
                float scale = (which == 0) ? 0.125f : 1.0f;
                float vx = (c[mi][j][2*half+0] + bb.x) * scale;
                float vy = (c[mi][j][2*half+1] + bb.y) * scale;
                __nv_bfloat16 h0 = __float2bfloat16(vx);
                __nv_bfloat16 h1 = __float2bfloat16(vy);
                __nv_bfloat162 hi2; hi2.x = h0; hi2.y = h1;
                __nv_bfloat162 lo2;
                lo2.x = __float2bfloat16(vx - __bfloat162float(h0));
                lo2.y = __float2bfloat16(vy - __bfloat162float(h1));
                if (which == 2) {
                    size_t vb = (((size_t)(b_*HEADS + h)*32 + (ns >> 6))*KATT
                                 + (ns & 63))*HDIM + d;
                    *(__nv_bfloat162*)&g_Vc[vb           ] = hi2;
                    *(__nv_bfloat162*)&g_Vc[vb + 64*HDIM ] = lo2;
                    *(__nv_bfloat162*)&g_Vc[vb + 128*HDIM] = hi2;
                } else {
                    __nv_bfloat16* dc = (which == 0) ? g_Qc : g_Kc;
                    size_t qb = ((size_t)(b_*HEADS + h)*SEQ + ns)*KATT + d;
                    if (which == 0) {  // [Qh|Qh|Ql]
                        *(__nv_bfloat162*)&dc[qb      ] = hi2;
                        *(__nv_bfloat162*)&dc[qb + 64 ] = hi2;
                        *(__nv_bfloat162*)&dc[qb + 128] = lo2;
                    } else {           // [Kh|Kl|Kh]
                        *(__nv_bfloat162*)&dc[qb      ] = hi2;
                        *(__nv_bfloat162*)&dc[qb + 64 ] = lo2;
                        *(__nv_bfloat162*)&dc[qb + 128] = hi2;
                    }
                }
            }
        }
    }
}

// ---------------------------------------------------------------------------
// Flash attention on HMMA. 64 q-rows, 4 warps, register-resident Q,
// double-buffered K and V with ONE cp.async group {K,V} per iteration
// (1 wait + 1 sync per iter). V tiles [keycat 192][d 64] via ldsm.trans.
// smem 106496 B -> 2 CTAs/SM. grid (32, 32), 128 thr.
// ---------------------------------------------------------------------------
#define ROWB 400            // K/Q smem pitch
#define VROWB 144           // V smem pitch
#define KB0 0
#define KB1 25600
#define VB0 51200
#define VB1 78848
#define SMEM_ATT 106496
#define KTILE_B (64*384)        // 24576 B per K tile in gmem
#define VTILE_B (KATT*HDIM*2)   // 24576 B per V tile in gmem

__device__ __forceinline__ void att_load_k(uint32_t dst, const char* src, int tid)
{
    #pragma unroll
    for (int r = 0; r < 12; r++) {          // 64 rows x 24 sectors (16B)
        int idx = tid + r*128;
        int row = idx / 24, sec = idx % 24;
        cp16(dst + row*ROWB + sec*16, src + row*384 + sec*16);
    }
}
__device__ __forceinline__ void att_load_v(uint32_t dst, const char* src, int tid)
{
    #pragma unroll
    for (int r = 0; r < 12; r++) {          // 192 rows x 8 sectors (16B)
        int idx = tid + r*128;
        int row = idx >> 3, sec = idx & 7;
        cp16(dst + row*VROWB + sec*16, src + row*128 + sec*16);
    }
}

__global__ __launch_bounds__(128) void attn_mma(float* __restrict__ out)
{
    extern __shared__ char smem[];
    uint32_t sb = smem_u32(smem);
    int tid = threadIdx.x, wid = tid >> 5, l = tid & 31;
    int hb = blockIdx.y, q0 = blockIdx.x * 64;

    const char* Qg = (const char*)(g_Qc + ((size_t)hb*SEQ + q0)*KATT);
    const char* Kg = (const char*)(g_Kc + (size_t)hb*SEQ*KATT);
    const char* Vg = (const char*)(g_Vc + (size_t)hb*32*KATT*HDIM);

    // startup group: Q (staged in VB1) + K0 + V0
    att_load_k(sb + VB1, Qg, tid);
    att_load_k(sb + KB0, Kg, tid);
    att_load_v(sb + VB0, Vg, tid);
    CP_COMMIT();
    CP_WAIT0();
    __syncthreads();

    // Q fragments -> registers (loop-invariant)
    uint32_t qf[12][4];
    #pragma unroll
    for (int kk = 0; kk < 12; kk++) {
        int row = wid*16 + (l & 15);
        int sec = 2*kk + (l >> 4);
        ldm4(qf[kk], sb + VB1 + row*ROWB + sec*16);
    }
    __syncthreads();                     // all warps done reading Q staging

    // pre-issue {K1, V1} (VB1 now free)
    att_load_k(sb + KB1, Kg + KTILE_B, tid);
    att_load_v(sb + VB1, Vg + VTILE_B, tid);
    CP_COMMIT();

    float o[8][4];
    #pragma unroll
    for (int j = 0; j < 8; j++)
        #pragma unroll
        for (int e = 0; e < 4; e++) o[j][e] = 0.f;
    float m0r = -1e30f, m1r = -1e30f, l0r = 0.f, l1r = 0.f;

    for (int i = 0; i < 32; i++) {
        if (i > 0) {
            CP_WAIT0();                  // {K_i, V_i} complete
            __syncthreads();             // also orders prev-iter reads before reuse
            if (i + 1 < 32) {
                att_load_k(sb + (((i+1) & 1) ? KB1 : KB0), Kg + (size_t)(i+1)*KTILE_B, tid);
                att_load_v(sb + (((i+1) & 1) ? VB1 : VB0), Vg + (size_t)(i+1)*VTILE_B, tid);
                CP_COMMIT();
            }
        }
        uint32_t kbase = sb + ((i & 1) ? KB1 : KB0);
        uint32_t vbase = sb + ((i & 1) ? VB1 : VB0);

        // ---- S = Qcat @ Kcat^T ----
        float s[8][4];
        #pragma unroll
        for (int j = 0; j < 8; j++)
            #pragma unroll
            for (int e = 0; e < 4; e++) s[j][e] = 0.f;

        #pragma unroll
        for (int kk = 0; kk < 12; kk++) {
            #pragma unroll
            for (int jp = 0; jp < 4; jp++) {
                uint32_t b[4];
                int row = jp*16 + (l & 7) + ((l >> 4) << 3);
                int sec = 2*kk + ((l >> 3) & 1);
                ldm4(b, kbase + row*ROWB + sec*16);
                mma16816(s[2*jp],   qf[kk], b[0], b[1]);
                mma16816(s[2*jp+1], qf[kk], b[2], b[3]);
            }
        }

        // ---- online softmax ----
        float rmax0 = -1e30f, rmax1 = -1e30f;
        #pragma unroll
        for (int j = 0; j < 8; j++) {
            rmax0 = fmaxf(rmax0, fmaxf(s[j][0], s[j][1]));
            rmax1 = fmaxf(rmax1, fmaxf(s[j][2], s[j][3]));
        }
        rmax0 = fmaxf(rmax0, __shfl_xor_sync(0xffffffffu, rmax0, 1));
        rmax0 = fmaxf(rmax0, __shfl_xor_sync(0xffffffffu, rmax0, 2));
        rmax1 = fmaxf(rmax1, __shfl_xor_sync(0xffffffffu, rmax1, 1));
        rmax1 = fmaxf(rmax1, __shfl_xor_sync(0xffffffffu, rmax1, 2));
        float nm0 = fmaxf(m0r, rmax0), nm1 = fmaxf(m1r, rmax1);
        float rs0 = 0.f, rs1 = 0.f;
        #pragma unroll
        for (int j = 0; j < 8; j++) {
            s[j][0] = __expf(s[j][0] - nm0);
            s[j][1] = __expf(s[j][1] - nm0);
            s[j][2] = __expf(s[j][2] - nm1);
            s[j][3] = __expf(s[j][3] - nm1);
            rs0 += s[j][0] + s[j][1];
            rs1 += s[j][2] + s[j][3];
        }
        rs0 += __shfl_xor_sync(0xffffffffu, rs0, 1);
        rs0 += __shfl_xor_sync(0xffffffffu, rs0, 2);
        rs1 += __shfl_xor_sync(0xffffffffu, rs1, 1);
        rs1 += __shfl_xor_sync(0xffffffffu, rs1, 2);
        float al0 = __expf(m0r - nm0), al1 = __expf(m1r - nm1);
        l0r = l0r*al0 + rs0;  l1r = l1r*al1 + rs1;
        m0r = nm0;  m1r = nm1;
        #pragma unroll
        for (int j = 0; j < 8; j++) {
            o[j][0] *= al0; o[j][1] *= al0;
            o[j][2] *= al1; o[j][3] *= al1;
        }

        // ---- pack P (hi + residual lo) into A fragments ----
        uint32_t ph[4][4], pl[4][4];
        #pragma unroll
        for (int kk = 0; kk < 4; kk++) {
            #pragma unroll
            for (int half = 0; half < 2; half++) {
                #pragma unroll
                for (int sub = 0; sub < 2; sub++) {
                    float p0 = s[2*kk+sub][2*half+0];
                    float p1 = s[2*kk+sub][2*half+1];
                    __nv_bfloat16 h0 = __float2bfloat16(p0);
                    __nv_bfloat16 h1 = __float2bfloat16(p1);
                    ph[kk][2*sub+half] = packbf2(h0, h1);
                    pl[kk][2*sub+half] = packbf2(
                        __float2bfloat16(p0 - __bfloat162float(h0)),
                        __float2bfloat16(p1 - __bfloat162float(h1)));
                }
            }
        }

        // ---- O += Pcat @ Vcat  (V in [keycat][d], B-frags via ldsm.trans) ----
        #pragma unroll
        for (int kb = 0; kb < 12; kb++) {
            const uint32_t* a = (kb < 4) ? ph[kb] : (kb < 8) ? ph[kb-4] : pl[kb-8];
            #pragma unroll
            for (int jp = 0; jp < 4; jp++) {
                uint32_t b[4];
                int row = kb*16 + (l & 7) + (((l >> 3) & 1) << 3);  // k-row
                int colb = jp*32 + ((l >> 4) << 4);                  // d-col bytes
                ldm4t(b, vbase + row*VROWB + colb);
                mma16816(o[2*jp],   a, b[0], b[1]);
                mma16816(o[2*jp+1], a, b[2], b[3]);
            }
        }
    }

    // ---- epilogue ----
    int b_ = hb >> 4, h = hb & 15;
    float inv0 = 1.f / l0r, inv1 = 1.f / l1r;
    int r0 = q0 + wid*16 + (l >> 2);
    #pragma unroll
    for (int j = 0; j < 8; j++) {
        int d = j*8 + (l & 3)*2;
        float2 v0; v0.x = o[j][0]*inv0; v0.y = o[j][1]*inv0;
        float2 v1; v1.x = o[j][2]*inv1; v1.y = o[j][3]*inv1;
        *(float2*)&out[((size_t)(b_*SEQ + r0  ))*EMBED + h*HDIM + d] = v0;
        *(float2*)&out[((size_t)(b_*SEQ + r0+8))*EMBED + h*HDIM + d] = v1;
    }
}

// ---------------------------------------------------------------------------
extern "C" void kernel_launch(void* const* d_in, const int* in_sizes, int n_in,
                              void* d_out, int out_size)
{
    const float* x  = (const float*)d_in[0];
    const float* Wq = (const float*)d_in[1];
    const float* bq = (const float*)d_in[2];
    const float* Wk = (const float*)d_in[3];
    const float* bk = (const float*)d_in[4];
    const float* Wv = (const float*)d_in[5];
    const float* bv = (const float*)d_in[6];
    const float* Wp = (const float*)d_in[7];
    float* out = (float*)d_out;

    cudaFuncSetAttribute(gemm_mma, cudaFuncAttributeMaxDynamicSharedMemorySize, SMEM_GEMM);
    cudaFuncSetAttribute(attn_mma, cudaFuncAttributeMaxDynamicSharedMemorySize, SMEM_ATT);

    prep_all<<<11266, 256>>>(x, Wq, bq, Wk, bk, Wv, Wp);                  // #1
    gemm_mma<<<dim3(MTOT/128, 24), 256, SMEM_GEMM>>>(bv);                 // #2
    attn_mma<<<dim3(SEQ/64, BATCH*HEADS), 128, SMEM_ATT>>>(out);          // #3
}

// round 11
// speedup vs baseline: 1.2024x; 1.0068x over previous
#include <cuda_runtime.h>
#include <cuda_bf16.h>
#include <cstdint>
#include <math.h>

#define EMBED 1024
#define HEADS 16
#define HDIM  64
#define BATCH 2
#define SEQ   2048
#define MTOT  (BATCH*SEQ)   // 4096
#define KCAT  3072          // 3*EMBED (split-bf16 concat)
#define KATT  192           // 3*HDIM  (split concat for attention)

// ---------------- scratch (device globals; no allocation allowed) ----------
__device__ float g_beffQ[EMBED];
__device__ float g_beffK[EMBED];
__device__ __align__(256) __nv_bfloat16 g_Xcat[MTOT*KCAT];      // [m][3072] = [Xh|Xh|Xl]
__device__ __align__(256) __nv_bfloat16 g_WcatQ[EMBED*KCAT];    // [n][3072] = [Wh|Wl|Wh]
__device__ __align__(256) __nv_bfloat16 g_WcatK[EMBED*KCAT];
__device__ __align__(256) __nv_bfloat16 g_WcatV[EMBED*KCAT];
__device__ __align__(256) __nv_bfloat16 g_Qc[32*SEQ*KATT];      // [hb][n][192] = [Qh|Qh|Ql]*0.125
__device__ __align__(256) __nv_bfloat16 g_Kc[32*SEQ*KATT];      // [hb][n][192] = [Kh|Kl|Kh]
__device__ __align__(256) __nv_bfloat16 g_Vc[32*32*KATT*HDIM];  // [hb][tile][keycat 192][d 64]

// ======================= PTX helpers (sm_80-level) =========================
__device__ __forceinline__ uint32_t smem_u32(const void* p) {
    uint32_t a;
    asm("{ .reg .u64 t; cvta.to.shared.u64 t, %1; cvt.u32.u64 %0, t; }" : "=r"(a) : "l"(p));
    return a;
}
__device__ __forceinline__ void cp16(uint32_t s, const void* g) {
    asm volatile("cp.async.cg.shared.global [%0], [%1], 16;" :: "r"(s), "l"(g));
}
#define CP_COMMIT() asm volatile("cp.async.commit_group;" ::: "memory")
#define CP_WAIT1()  asm volatile("cp.async.wait_group 1;" ::: "memory")
#define CP_WAIT0()  asm volatile("cp.async.wait_group 0;" ::: "memory")

__device__ __forceinline__ void mma16816(float* c, const uint32_t* a, uint32_t b0, uint32_t b1) {
    asm volatile("mma.sync.aligned.m16n8k16.row.col.f32.bf16.bf16.f32 "
        "{%0,%1,%2,%3}, {%4,%5,%6,%7}, {%8,%9}, {%0,%1,%2,%3};"
        : "+f"(c[0]), "+f"(c[1]), "+f"(c[2]), "+f"(c[3])
        : "r"(a[0]), "r"(a[1]), "r"(a[2]), "r"(a[3]), "r"(b0), "r"(b1));
}
__device__ __forceinline__ void ldm4(uint32_t* r, uint32_t addr) {
    asm volatile("ldmatrix.sync.aligned.m8n8.x4.shared.b16 {%0,%1,%2,%3}, [%4];"
        : "=r"(r[0]), "=r"(r[1]), "=r"(r[2]), "=r"(r[3]) : "r"(addr));
}
__device__ __forceinline__ void ldm4t(uint32_t* r, uint32_t addr) {
    asm volatile("ldmatrix.sync.aligned.m8n8.x4.trans.shared.b16 {%0,%1,%2,%3}, [%4];"
        : "=r"(r[0]), "=r"(r[1]), "=r"(r[2]), "=r"(r[3]) : "r"(addr));
}
__device__ __forceinline__ uint32_t packbf2(__nv_bfloat16 lo, __nv_bfloat16 hi) {
    __nv_bfloat162 t; t.x = lo; t.y = hi;
    return *(uint32_t*)&t;
}
__device__ __forceinline__ uint32_t hi2of(float a, float b) {
    __nv_bfloat162 t; t.x = __float2bfloat16(a); t.y = __float2bfloat16(b);
    return *(uint32_t*)&t;
}

// ---------------------------------------------------------------------------
// ONE prep kernel, block-range dispatch:
//   [0, 2048)       : X -> split-bf16 K-concat (8 elems/thread, 16B stores)
//   [2048, 4096)    : Wq/Wk: fold Wp AND split-convert (32x32 Weff tile)
//   [4096, 5120)    : Wv: transpose + split-convert
//   [5120, 5122)    : bias fold for Q / K
// ---------------------------------------------------------------------------
__global__ __launch_bounds__(256) void prep_all(
    const float* __restrict__ x,
    const float* __restrict__ Wq, const float* __restrict__ bq,
    const float* __restrict__ Wk, const float* __restrict__ bk,
    const float* __restrict__ Wv, const float* __restrict__ Wp)
{
    __shared__ float tile[32][33];
    __shared__ float WrowS[32][65];
    __shared__ float WpS[64][32];
    int bx = blockIdx.x;
    int tid = threadIdx.x;

    if (bx < 2048) {                                   // ---- X convert ----
        int t = bx*256 + tid;                          // 8 elems per thread
        const float4* xp = (const float4*)x;
        float4 a = xp[t*2], b4 = xp[t*2+1];
        int m = t >> 7;
        int e = (t & 127) << 3;
        uint4 hi, lo;
        hi.x = hi2of(a.x,  a.y);  hi.y = hi2of(a.z,  a.w);
        hi.z = hi2of(b4.x, b4.y); hi.w = hi2of(b4.z, b4.w);
        __nv_bfloat162* hp = (__nv_bfloat162*)&hi;
        lo.x = hi2of(a.x  - __bfloat162float(hp[0].x), a.y  - __bfloat162float(hp[0].y));
        lo.y = hi2of(a.z  - __bfloat162float(hp[1].x), a.w  - __bfloat162float(hp[1].y));
        lo.z = hi2of(b4.x - __bfloat162float(hp[2].x), b4.y - __bfloat162float(hp[2].y));
        lo.w = hi2of(b4.z - __bfloat162float(hp[3].x), b4.w - __bfloat162float(hp[3].y));
        size_t base = (size_t)m*KCAT + e;
        *(uint4*)&g_Xcat[base        ] = hi;
        *(uint4*)&g_Xcat[base + 1024 ] = hi;
        *(uint4*)&g_Xcat[base + 2048 ] = lo;
        return;
    }

    int tx = tid & 31, ty = tid >> 5;                  // (32, 8)

    if (bx < 4096) {                                   // ---- Wq/Wk fold+convert ----
        int wb = bx - 2048;
        int z  = wb >> 10;                             // 0=Q, 1=K
        int rem = wb & 1023;
        int e0 = (rem >> 5) * 32;
        int n0 = (rem & 31) * 32;
        int h  = n0 >> 6, i0 = n0 & 63;
        const float* W = z ? Wk : Wq;
        __nv_bfloat16* dst = z ? g_WcatK : g_WcatQ;

        #pragma unroll
        for (int r = 0; r < 8; r++) {
            int idx = tid + r*256;                     // 2048 elems
            int e = idx >> 6, d = idx & 63;
            WrowS[e][d] = W[(size_t)(e0+e)*EMBED + h*HDIM + d];
            int dd = idx >> 5, ni = idx & 31;
            WpS[dd][ni] = Wp[dd*HDIM + i0 + ni];
        }
        __syncthreads();
        #pragma unroll
        for (int j = 0; j < 32; j += 8) {
            int n = ty + j;
            float acc = 0.f;
            #pragma unroll 8
            for (int d = 0; d < 64; d++)
                acc = fmaf(WrowS[tx][d], WpS[d][n], acc);
            tile[tx][n] = acc;
        }
        __syncthreads();
        #pragma unroll
        for (int j = 0; j < 32; j += 8) {
            int n = ty + j;
            float v = tile[tx][n];
            __nv_bfloat16 hi = __float2bfloat16(v);
            __nv_bfloat16 lo = __float2bfloat16(v - __bfloat162float(hi));
            size_t base = (size_t)(n0+n)*KCAT + e0 + tx;
            dst[base       ] = hi;
            dst[base + 1024] = lo;
            dst[base + 2048] = hi;
        }
        return;
    }

    if (bx < 5120) {                                   // ---- Wv transpose+convert ----
        int rem = bx - 4096;
        int k0 = (rem >> 5) * 32;
        int n0 = (rem & 31) * 32;
        #pragma unroll
        for (int j = 0; j < 32; j += 8)
            tile[ty+j][tx] = Wv[(size_t)(k0+ty+j)*EMBED + n0 + tx];
        __syncthreads();
        #pragma unroll
        for (int j = 0; j < 32; j += 8) {
            int n = ty + j;
            float v = tile[tx][n];
            __nv_bfloat16 hi = __float2bfloat16(v);
            __nv_bfloat16 lo = __float2bfloat16(v - __bfloat162float(hi));
            size_t base = (size_t)(n0+n)*KCAT + k0 + tx;
            g_WcatV[base       ] = hi;
            g_WcatV[base + 1024] = lo;
            g_WcatV[base + 2048] = hi;
        }
        return;
    }

    // ---- bias fold: beff[n] = sum_d b[h*64+d] * Wp[d][n&63] ----
    {
        int z = bx - 5120;                             // 0=Q, 1=K
        const float* b = z ? bk : bq;
        float* beff = z ? g_beffK : g_beffQ;
        #pragma unroll
        for (int r = 0; r < 4; r++) {
            int n = tid + r*256;
            int h = n >> 6, i = n & 63;
            float acc = 0.f;
            #pragma unroll 8
            for (int d = 0; d < 64; d++)
                acc = fmaf(b[h*HDIM + d], Wp[d*HDIM + i], acc);
            beff[n] = acc;
        }
    }
}

// ---------------------------------------------------------------------------
// Fused QKV HMMA GEMM, one launch, 2 CTAs/SM. grid (32, 24): which = by>>3.
// ---------------------------------------------------------------------------
#define GSTAGE 32768
#define SMEM_GEMM (2*GSTAGE)
#define NCHUNK (KCAT/64)   // 48

__device__ __forceinline__ void gemm_load(const __nv_bfloat16* Bw,
                                          uint32_t sb, int stage, int m0, int n0,
                                          int chunk, int tid)
{
    uint32_t as = sb + stage*GSTAGE;
    uint32_t bs = as + 16384;
    const char* Ac = (const char*)g_Xcat;
    const char* Bc = (const char*)Bw;
    #pragma unroll
    for (int r = 0; r < 4; r++) {
        int idx = tid + r*256;
        int row = idx >> 3, sec = idx & 7;
        cp16(as + row*128 + (((sec ^ (row & 7))) << 4),
             Ac + ((size_t)(m0+row)*KCAT + chunk*64 + sec*8)*2);
    }
    #pragma unroll
    for (int r = 0; r < 4; r++) {
        int idx = tid + r*256;
        int row = idx >> 3, sec = idx & 7;
        cp16(bs + row*128 + (((sec ^ (row & 7))) << 4),
             Bc + ((size_t)(n0+row)*KCAT + chunk*64 + sec*8)*2);
    }
}

__global__ __launch_bounds__(256, 2) void gemm_mma(const float* __restrict__ bv)
{
    extern __shared__ char smem[];
    uint32_t sb = smem_u32(smem);
    int tid = threadIdx.x, wid = tid >> 5, l = tid & 31;
    int which = blockIdx.y >> 3;                       // 0=Q, 1=K, 2=V
    int m0 = blockIdx.x * 128, n0 = (blockIdx.y & 7) * 128;
    int wm = (wid & 3) * 32, wn = (wid >> 2) * 64;

    const __nv_bfloat16* Bw = (which == 0) ? g_WcatQ : (which == 1) ? g_WcatK : g_WcatV;
    const float* bias = (which == 0) ? g_beffQ : (which == 1) ? g_beffK : bv;

    float c[2][8][4];
    #pragma unroll
    for (int mi = 0; mi < 2; mi++)
        #pragma unroll
        for (int j = 0; j < 8; j++)
            #pragma unroll
            for (int e = 0; e < 4; e++) c[mi][j][e] = 0.f;

    gemm_load(Bw, sb, 0, m0, n0, 0, tid);
    CP_COMMIT();

    for (int i = 0; i < NCHUNK; i++) {
        if (i + 1 < NCHUNK) {
            gemm_load(Bw, sb, (i+1) & 1, m0, n0, i+1, tid);
            CP_COMMIT();
            CP_WAIT1();
        } else {
            CP_WAIT0();
        }
        __syncthreads();

        uint32_t as = sb + (i & 1)*GSTAGE;
        uint32_t bs = as + 16384;
        #pragma unroll
        for (int kk = 0; kk < 4; kk++) {
            uint32_t a0[4], a1[4];
            {
                int row = wm + (l & 15);
                int sec = 2*kk + (l >> 4);
                ldm4(a0, as + row*128 + ((sec ^ (row & 7)) << 4));
                row += 16;
                ldm4(a1, as + row*128 + ((sec ^ (row & 7)) << 4));
            }
            #pragma unroll
            for (int jp = 0; jp < 4; jp++) {
                uint32_t b[4];
                int row = wn + jp*16 + (l & 7) + ((l >> 4) << 3);
                int sec = 2*kk + ((l >> 3) & 1);
                ldm4(b, bs + row*128 + ((sec ^ (row & 7)) << 4));
                mma16816(c[0][2*jp],   a0, b[0], b[1]);
                mma16816(c[0][2*jp+1], a0, b[2], b[3]);
                mma16816(c[1][2*jp],   a1, b[0], b[1]);
                mma16816(c[1][2*jp+1], a1, b[2], b[3]);
            }
        }
        __syncthreads();
    }

    // ---- epilogue (all outputs split-bf16) ----
    #pragma unroll
    for (int mi = 0; mi < 2; mi++) {
        int mbase = m0 + wm + mi*16 + (l >> 2);
        #pragma unroll
        for (int j = 0; j < 8; j++) {
            int ncol = n0 + wn + j*8 + (l & 3)*2;
            float2 bb = *(const float2*)&bias[ncol];
            int h = ncol >> 6, d = ncol & 63;
            #pragma unroll
            for (int half = 0; half < 2; half++) {
                int m = mbase + half*8;
                int b_ = m >> 11, ns = m & (SEQ-1);
                float scale = (which == 0) ? 0.125f : 1.0f;
                float vx = (c[mi][j][2*half+0] + bb.x) * scale;
                float vy = (c[mi][j][2*half+1] + bb.y) * scale;
                __nv_bfloat16 h0 = __float2bfloat16(vx);
                __nv_bfloat16 h1 = __float2bfloat16(vy);
                __nv_bfloat162 hi2; hi2.x = h0; hi2.y = h1;
                __nv_bfloat162 lo2;
                lo2.x = __float2bfloat16(vx - __bfloat162float(h0));
                lo2.y = __float2bfloat16(vy - __bfloat162float(h1));
                if (which == 2) {
                    size_t vb = (((size_t)(b_*HEADS + h)*32 + (ns >> 6))*KATT
                                 + (ns & 63))*HDIM + d;
                    *(__nv_bfloat162*)&g_Vc[vb           ] = hi2;
                    *(__nv_bfloat162*)&g_Vc[vb + 64*HDIM ] = lo2;
                    *(__nv_bfloat162*)&g_Vc[vb + 128*HDIM] = hi2;
                } else {
                    __nv_bfloat16* dc = (which == 0) ? g_Qc : g_Kc;
                    size_t qb = ((size_t)(b_*HEADS + h)*SEQ + ns)*KATT + d;
                    if (which == 0) {  // [Qh|Qh|Ql]
                        *(__nv_bfloat162*)&dc[qb      ] = hi2;
                        *(__nv_bfloat162*)&dc[qb + 64 ] = hi2;
                        *(__nv_bfloat162*)&dc[qb + 128] = lo2;
                    } else {           // [Kh|Kl|Kh]
                        *(__nv_bfloat162*)&dc[qb      ] = hi2;
                        *(__nv_bfloat162*)&dc[qb + 64 ] = lo2;
                        *(__nv_bfloat162*)&dc[qb + 128] = hi2;
                    }
                }
            }
        }
    }
}

// ---------------------------------------------------------------------------
// Flash attention on HMMA (unchanged from round 10 win).
// ---------------------------------------------------------------------------
#define ROWB 400            // K/Q smem pitch
#define VROWB 144           // V smem pitch
#define KB0 0
#define KB1 25600
#define VB0 51200
#define VB1 78848
#define SMEM_ATT 106496
#define KTILE_B (64*384)        // 24576 B per K tile in gmem
#define VTILE_B (KATT*HDIM*2)   // 24576 B per V tile in gmem

__device__ __forceinline__ void att_load_k(uint32_t dst, const char* src, int tid)
{
    #pragma unroll
    for (int r = 0; r < 12; r++) {          // 64 rows x 24 sectors (16B)
        int idx = tid + r*128;
        int row = idx / 24, sec = idx % 24;
        cp16(dst + row*ROWB + sec*16, src + row*384 + sec*16);
    }
}
__device__ __forceinline__ void att_load_v(uint32_t dst, const char* src, int tid)
{
    #pragma unroll
    for (int r = 0; r < 12; r++) {          // 192 rows x 8 sectors (16B)
        int idx = tid + r*128;
        int row = idx >> 3, sec = idx & 7;
        cp16(dst + row*VROWB + sec*16, src + row*128 + sec*16);
    }
}

__global__ __launch_bounds__(128) void attn_mma(float* __restrict__ out)
{
    extern __shared__ char smem[];
    uint32_t sb = smem_u32(smem);
    int tid = threadIdx.x, wid = tid >> 5, l = tid & 31;
    int hb = blockIdx.y, q0 = blockIdx.x * 64;

    const char* Qg = (const char*)(g_Qc + ((size_t)hb*SEQ + q0)*KATT);
    const char* Kg = (const char*)(g_Kc + (size_t)hb*SEQ*KATT);
    const char* Vg = (const char*)(g_Vc + (size_t)hb*32*KATT*HDIM);

    // startup group: Q (staged in VB1) + K0 + V0
    att_load_k(sb + VB1, Qg, tid);
    att_load_k(sb + KB0, Kg, tid);
    att_load_v(sb + VB0, Vg, tid);
    CP_COMMIT();
    CP_WAIT0();
    __syncthreads();

    // Q fragments -> registers (loop-invariant)
    uint32_t qf[12][4];
    #pragma unroll
    for (int kk = 0; kk < 12; kk++) {
        int row = wid*16 + (l & 15);
        int sec = 2*kk + (l >> 4);
        ldm4(qf[kk], sb + VB1 + row*ROWB + sec*16);
    }
    __syncthreads();                     // all warps done reading Q staging

    // pre-issue {K1, V1} (VB1 now free)
    att_load_k(sb + KB1, Kg + KTILE_B, tid);
    att_load_v(sb + VB1, Vg + VTILE_B, tid);
    CP_COMMIT();

    float o[8][4];
    #pragma unroll
    for (int j = 0; j < 8; j++)
        #pragma unroll
        for (int e = 0; e < 4; e++) o[j][e] = 0.f;
    float m0r = -1e30f, m1r = -1e30f, l0r = 0.f, l1r = 0.f;

    for (int i = 0; i < 32; i++) {
        if (i > 0) {
            CP_WAIT0();                  // {K_i, V_i} complete
            __syncthreads();             // also orders prev-iter reads before reuse
            if (i + 1 < 32) {
                att_load_k(sb + (((i+1) & 1) ? KB1 : KB0), Kg + (size_t)(i+1)*KTILE_B, tid);
                att_load_v(sb + (((i+1) & 1) ? VB1 : VB0), Vg + (size_t)(i+1)*VTILE_B, tid);
                CP_COMMIT();
            }
        }
        uint32_t kbase = sb + ((i & 1) ? KB1 : KB0);
        uint32_t vbase = sb + ((i & 1) ? VB1 : VB0);

        // ---- S = Qcat @ Kcat^T ----
        float s[8][4];
        #pragma unroll
        for (int j = 0; j < 8; j++)
            #pragma unroll
            for (int e = 0; e < 4; e++) s[j][e] = 0.f;

        #pragma unroll
        for (int kk = 0; kk < 12; kk++) {
            #pragma unroll
            for (int jp = 0; jp < 4; jp++) {
                uint32_t b[4];
                int row = jp*16 + (l & 7) + ((l >> 4) << 3);
                int sec = 2*kk + ((l >> 3) & 1);
                ldm4(b, kbase + row*ROWB + sec*16);
                mma16816(s[2*jp],   qf[kk], b[0], b[1]);
                mma16816(s[2*jp+1], qf[kk], b[2], b[3]);
            }
        }

        // ---- online softmax ----
        float rmax0 = -1e30f, rmax1 = -1e30f;
        #pragma unroll
        for (int j = 0; j < 8; j++) {
            rmax0 = fmaxf(rmax0, fmaxf(s[j][0], s[j][1]));
            rmax1 = fmaxf(rmax1, fmaxf(s[j][2], s[j][3]));
        }
        rmax0 = fmaxf(rmax0, __shfl_xor_sync(0xffffffffu, rmax0, 1));
        rmax0 = fmaxf(rmax0, __shfl_xor_sync(0xffffffffu, rmax0, 2));
        rmax1 = fmaxf(rmax1, __shfl_xor_sync(0xffffffffu, rmax1, 1));
        rmax1 = fmaxf(rmax1, __shfl_xor_sync(0xffffffffu, rmax1, 2));
        float nm0 = fmaxf(m0r, rmax0), nm1 = fmaxf(m1r, rmax1);
        float rs0 = 0.f, rs1 = 0.f;
        #pragma unroll
        for (int j = 0; j < 8; j++) {
            s[j][0] = __expf(s[j][0] - nm0);
            s[j][1] = __expf(s[j][1] - nm0);
            s[j][2] = __expf(s[j][2] - nm1);
            s[j][3] = __expf(s[j][3] - nm1);
            rs0 += s[j][0] + s[j][1];
            rs1 += s[j][2] + s[j][3];
        }
        rs0 += __shfl_xor_sync(0xffffffffu, rs0, 1);
        rs0 += __shfl_xor_sync(0xffffffffu, rs0, 2);
        rs1 += __shfl_xor_sync(0xffffffffu, rs1, 1);
        rs1 += __shfl_xor_sync(0xffffffffu, rs1, 2);
        float al0 = __expf(m0r - nm0), al1 = __expf(m1r - nm1);
        l0r = l0r*al0 + rs0;  l1r = l1r*al1 + rs1;
        m0r = nm0;  m1r = nm1;
        #pragma unroll
        for (int j = 0; j < 8; j++) {
            o[j][0] *= al0; o[j][1] *= al0;
            o[j][2] *= al1; o[j][3] *= al1;
        }

        // ---- pack P (hi + residual lo) into A fragments ----
        uint32_t ph[4][4], pl[4][4];
        #pragma unroll
        for (int kk = 0; kk < 4; kk++) {
            #pragma unroll
            for (int half = 0; half < 2; half++) {
                #pragma unroll
                for (int sub = 0; sub < 2; sub++) {
                    float p0 = s[2*kk+sub][2*half+0];
                    float p1 = s[2*kk+sub][2*half+1];
                    __nv_bfloat16 h0 = __float2bfloat16(p0);
                    __nv_bfloat16 h1 = __float2bfloat16(p1);
                    ph[kk][2*sub+half] = packbf2(h0, h1);
                    pl[kk][2*sub+half] = packbf2(
                        __float2bfloat16(p0 - __bfloat162float(h0)),
                        __float2bfloat16(p1 - __bfloat162float(h1)));
                }
            }
        }

        // ---- O += Pcat @ Vcat  (V in [keycat][d], B-frags via ldsm.trans) ----
        #pragma unroll
        for (int kb = 0; kb < 12; kb++) {
            const uint32_t* a = (kb < 4) ? ph[kb] : (kb < 8) ? ph[kb-4] : pl[kb-8];
            #pragma unroll
            for (int jp = 0; jp < 4; jp++) {
                uint32_t b[4];
                int row = kb*16 + (l & 7) + (((l >> 3) & 1) << 3);  // k-row
                int colb = jp*32 + ((l >> 4) << 4);                  // d-col bytes
                ldm4t(b, vbase + row*VROWB + colb);
                mma16816(o[2*jp],   a, b[0], b[1]);
                mma16816(o[2*jp+1], a, b[2], b[3]);
            }
        }
    }

    // ---- epilogue ----
    int b_ = hb >> 4, h = hb & 15;
    float inv0 = 1.f / l0r, inv1 = 1.f / l1r;
    int r0 = q0 + wid*16 + (l >> 2);
    #pragma unroll
    for (int j = 0; j < 8; j++) {
        int d = j*8 + (l & 3)*2;
        float2 v0; v0.x = o[j][0]*inv0; v0.y = o[j][1]*inv0;
        float2 v1; v1.x = o[j][2]*inv1; v1.y = o[j][3]*inv1;
        *(float2*)&out[((size_t)(b_*SEQ + r0  ))*EMBED + h*HDIM + d] = v0;
        *(float2*)&out[((size_t)(b_*SEQ + r0+8))*EMBED + h*HDIM + d] = v1;
    }
}

// ---------------------------------------------------------------------------
extern "C" void kernel_launch(void* const* d_in, const int* in_sizes, int n_in,
                              void* d_out, int out_size)
{
    const float* x  = (const float*)d_in[0];
    const float* Wq = (const float*)d_in[1];
    const float* bq = (const float*)d_in[2];
    const float* Wk = (const float*)d_in[3];
    const float* bk = (const float*)d_in[4];
    const float* Wv = (const float*)d_in[5];
    const float* bv = (const float*)d_in[6];
    const float* Wp = (const float*)d_in[7];
    float* out = (float*)d_out;

    cudaFuncSetAttribute(gemm_mma, cudaFuncAttributeMaxDynamicSharedMemorySize, SMEM_GEMM);
    cudaFuncSetAttribute(attn_mma, cudaFuncAttributeMaxDynamicSharedMemorySize, SMEM_ATT);

    prep_all<<<5122, 256>>>(x, Wq, bq, Wk, bk, Wv, Wp);                   // #1
    gemm_mma<<<dim3(MTOT/128, 24), 256, SMEM_GEMM>>>(bv);                 // #2
    attn_mma<<<dim3(SEQ/64, BATCH*HEADS), 128, SMEM_ATT>>>(out);          // #3
}